// round 1
// baseline (speedup 1.0000x reference)
#include <cuda_runtime.h>

// Problem constants (fixed shapes from reference setup_inputs)
#define TT 4
#define BB 32
#define CC 256
#define HH 32
#define WW 32
#define HW 1024          // HH*WW
#define TB 128           // TT*BB
#define NSTAT 131072.0f  // TB*HW, BN reduction size
#define EPSV 1e-5f

// Per-channel stat accumulators + packed spike bits (4 MB)
__device__ float g_sum1[CC], g_sumsq1[CC], g_sum2[CC], g_sumsq2[CC];
__device__ unsigned g_spk[(TT * BB * CC * HW) / 32];

// ---------------------------------------------------------------------------
// K0: zero stats (graph replays must start clean every launch)
// ---------------------------------------------------------------------------
__global__ void k_zero_stats() {
    int i = threadIdx.x;  // 256 threads == CC
    g_sum1[i] = 0.f; g_sumsq1[i] = 0.f;
    g_sum2[i] = 0.f; g_sumsq2[i] = 0.f;
}

// ---------------------------------------------------------------------------
// Block-wide reduction of two floats; result valid in thread 0.
// ---------------------------------------------------------------------------
__device__ __forceinline__ void block_reduce2(float& a, float& b) {
    #pragma unroll
    for (int o = 16; o > 0; o >>= 1) {
        a += __shfl_xor_sync(0xffffffffu, a, o);
        b += __shfl_xor_sync(0xffffffffu, b, o);
    }
    __shared__ float sa[8], sb[8];
    int warp = threadIdx.x >> 5, lane = threadIdx.x & 31;
    if (lane == 0) { sa[warp] = a; sb[warp] = b; }
    __syncthreads();
    if (threadIdx.x == 0) {
        float ta = 0.f, tb = 0.f;
        #pragma unroll
        for (int i = 0; i < 8; i++) { ta += sa[i]; tb += sb[i]; }
        a = ta; b = tb;
    }
}

// ---------------------------------------------------------------------------
// K1: depthwise 3x3 conv + bias, accumulate per-channel sum / sumsq (BN1 stats)
// One block per (n, c) plane; 256 threads, 4 pixels each.
// ---------------------------------------------------------------------------
__global__ void __launch_bounds__(256) k_conv_stats(
    const float* __restrict__ x, const float* __restrict__ cw,
    const float* __restrict__ cb)
{
    const int n = blockIdx.x >> 8;        // 0..127  (blockIdx.x / CC)
    const int c = blockIdx.x & (CC - 1);  // 0..255
    const float* xp = x + (size_t)(n * CC + c) * HW;

    __shared__ float tile[34 * 34];
    for (int i = threadIdx.x; i < 34 * 34; i += 256) {
        int hy = i / 34 - 1, hx = i % 34 - 1;
        float v = 0.f;
        if (hy >= 0 && hy < HH && hx >= 0 && hx < WW) v = xp[hy * WW + hx];
        tile[i] = v;
    }

    float wgt[9];
    #pragma unroll
    for (int i = 0; i < 9; i++) wgt[i] = __ldg(&cw[c * 9 + i]);
    const float bias = __ldg(&cb[c]);
    __syncthreads();

    float s = 0.f, ss = 0.f;
    #pragma unroll
    for (int k = 0; k < 4; k++) {
        int p = threadIdx.x + k * 256;
        int r = p >> 5, q = p & 31;
        const float* t0 = &tile[r * 34 + q];
        float acc = bias
            + wgt[0] * t0[0]  + wgt[1] * t0[1]  + wgt[2] * t0[2]
            + wgt[3] * t0[34] + wgt[4] * t0[35] + wgt[5] * t0[36]
            + wgt[6] * t0[68] + wgt[7] * t0[69] + wgt[8] * t0[70];
        s += acc; ss += acc * acc;
    }
    block_reduce2(s, ss);
    if (threadIdx.x == 0) {
        atomicAdd(&g_sum1[c], s);
        atomicAdd(&g_sumsq1[c], ss);
    }
}

// ---------------------------------------------------------------------------
// K3: recompute conv for all 4 timesteps, apply BN1 (folded scale/shift),
// run the LIF dynamics, pack spikes into bits via ballot, and accumulate
// BN2 stats of z = spike + x.
// One block per (b, c); 4 halo planes in smem (18.5 KB).
// ---------------------------------------------------------------------------
__global__ void __launch_bounds__(256) k_lif(
    const float* __restrict__ x, const float* __restrict__ cw,
    const float* __restrict__ cb, const float* __restrict__ g1,
    const float* __restrict__ b1)
{
    const int b = blockIdx.x >> 8;        // 0..31
    const int c = blockIdx.x & (CC - 1);  // 0..255

    __shared__ float tile[TT][34 * 34];
    #pragma unroll
    for (int t = 0; t < TT; t++) {
        const float* xp = x + (size_t)((t * BB + b) * CC + c) * HW;
        for (int i = threadIdx.x; i < 34 * 34; i += 256) {
            int hy = i / 34 - 1, hx = i % 34 - 1;
            float v = 0.f;
            if (hy >= 0 && hy < HH && hx >= 0 && hx < WW) v = xp[hy * WW + hx];
            tile[t][i] = v;
        }
    }

    float wgt[9];
    #pragma unroll
    for (int i = 0; i < 9; i++) wgt[i] = __ldg(&cw[c * 9 + i]);

    // Fold BN1 (+ conv bias) into scale/shift: y = conv*scale1 + shift1
    const float mean1  = g_sum1[c] * (1.f / NSTAT);
    const float var1   = g_sumsq1[c] * (1.f / NSTAT) - mean1 * mean1;
    const float scale1 = __ldg(&g1[c]) * rsqrtf(var1 + EPSV);
    const float shift1 = __ldg(&b1[c]) + (__ldg(&cb[c]) - mean1) * scale1;
    __syncthreads();

    const int warp = threadIdx.x >> 5;
    const int lane = threadIdx.x & 31;

    float s2 = 0.f, ss2 = 0.f;
    #pragma unroll
    for (int k = 0; k < 4; k++) {
        const int r = warp * 4 + k;  // output row
        const int q = lane;          // output col
        float v = 0.f;               // membrane potential
        #pragma unroll
        for (int t = 0; t < TT; t++) {
            const float* t0 = &tile[t][r * 34 + q];
            float conv =
                  wgt[0] * t0[0]  + wgt[1] * t0[1]  + wgt[2] * t0[2]
                + wgt[3] * t0[34] + wgt[4] * t0[35] + wgt[5] * t0[36]
                + wgt[6] * t0[68] + wgt[7] * t0[69] + wgt[8] * t0[70];
            float y = conv * scale1 + shift1;
            float h = 0.5f * (v + y);            // v + (y - v)/tau, tau = 2
            bool  fire = (h >= 1.0f);
            v = fire ? 0.f : h;                  // hard reset to 0
            float z = (fire ? 1.f : 0.f) + t0[35];  // spike + x (center)
            s2 += z; ss2 += z * z;
            unsigned m = __ballot_sync(0xffffffffu, fire);
            if (lane == 0)
                g_spk[((t * BB + b) * CC + c) * 32 + r] = m;
        }
    }
    block_reduce2(s2, ss2);
    if (threadIdx.x == 0) {
        atomicAdd(&g_sum2[c], s2);
        atomicAdd(&g_sumsq2[c], ss2);
    }
}

// ---------------------------------------------------------------------------
// K4: out = BN2(spike + x). float4 per thread, spike bits broadcast from word.
// ---------------------------------------------------------------------------
__global__ void __launch_bounds__(256) k_bn2(
    const float* __restrict__ x, const float* __restrict__ g2,
    const float* __restrict__ b2, float* __restrict__ out)
{
    const unsigned i4 = blockIdx.x * 256u + threadIdx.x;  // float4 index
    const unsigned e  = i4 * 4u;                          // element index
    const int c = (int)((e >> 10) & (CC - 1));            // (e/1024) % 256

    const float mean2  = g_sum2[c] * (1.f / NSTAT);
    const float var2   = g_sumsq2[c] * (1.f / NSTAT) - mean2 * mean2;
    const float scale2 = __ldg(&g2[c]) * rsqrtf(var2 + EPSV);
    const float shift2 = __ldg(&b2[c]) - mean2 * scale2;

    const float4 xv = reinterpret_cast<const float4*>(x)[i4];
    const unsigned wbits = g_spk[e >> 5];
    const int l = e & 31;

    float4 o;
    o.x = (xv.x + (float)((wbits >> (l + 0)) & 1u)) * scale2 + shift2;
    o.y = (xv.y + (float)((wbits >> (l + 1)) & 1u)) * scale2 + shift2;
    o.z = (xv.z + (float)((wbits >> (l + 2)) & 1u)) * scale2 + shift2;
    o.w = (xv.w + (float)((wbits >> (l + 3)) & 1u)) * scale2 + shift2;
    reinterpret_cast<float4*>(out)[i4] = o;
}

// ---------------------------------------------------------------------------
// Launch: 4 kernels, stream-ordered (gives the two global-stat barriers).
// ---------------------------------------------------------------------------
extern "C" void kernel_launch(void* const* d_in, const int* in_sizes, int n_in,
                              void* d_out, int out_size) {
    const float* x  = (const float*)d_in[0];
    const float* cw = (const float*)d_in[1];
    const float* cb = (const float*)d_in[2];
    const float* g1 = (const float*)d_in[3];
    const float* b1 = (const float*)d_in[4];
    const float* g2 = (const float*)d_in[5];
    const float* b2 = (const float*)d_in[6];
    float* out = (float*)d_out;

    k_zero_stats<<<1, 256>>>();
    k_conv_stats<<<TB * CC, 256>>>(x, cw, cb);           // 32768 blocks
    k_lif<<<BB * CC, 256>>>(x, cw, cb, g1, b1);          // 8192 blocks
    k_bn2<<<(TT * BB * CC * HW) / (256 * 4), 256>>>(x, g2, b2, out);  // 32768
}

// round 2
// speedup vs baseline: 1.6486x; 1.6486x over previous
#include <cuda_runtime.h>

// Problem constants (fixed shapes from reference setup_inputs)
#define TT 4
#define BB 32
#define CC 256
#define HH 32
#define WW 32
#define HW 1024          // HH*WW
#define TB 128           // TT*BB
#define NSTAT 131072.0   // TB*HW, BN reduction size (double)
#define EPSV 1e-5
#define TS 35            // smem tile row stride (34 cols padded to 35: conflict-free)

// Per-channel stat accumulators (double for accuracy) + packed spike bits (4MB)
__device__ double g_sum1[CC], g_sumsq1[CC], g_sum2[CC], g_sumsq2[CC];
__device__ unsigned g_spk[(TT * BB * CC * HW) / 32];

// ---------------------------------------------------------------------------
// Block-wide reduction of two floats; result valid in thread 0.
// ---------------------------------------------------------------------------
__device__ __forceinline__ void block_reduce2(float& a, float& b) {
    #pragma unroll
    for (int o = 16; o > 0; o >>= 1) {
        a += __shfl_xor_sync(0xffffffffu, a, o);
        b += __shfl_xor_sync(0xffffffffu, b, o);
    }
    __shared__ float sa[8], sb[8];
    int warp = threadIdx.x >> 5, lane = threadIdx.x & 31;
    if (lane == 0) { sa[warp] = a; sb[warp] = b; }
    __syncthreads();
    if (threadIdx.x == 0) {
        float ta = 0.f, tb = 0.f;
        #pragma unroll
        for (int i = 0; i < 8; i++) { ta += sa[i]; tb += sb[i]; }
        a = ta; b = tb;
    }
}

// ---------------------------------------------------------------------------
// Fast halo-tile loader: border is zero padding; interior is one float4/thread.
// tile is 34 rows x stride TS(35). Valid cols 0..33, valid rows 0..33.
// ---------------------------------------------------------------------------
__device__ __forceinline__ void load_plane(const float* __restrict__ xp,
                                           float* __restrict__ tile) {
    const int tid = threadIdx.x;
    if (tid < 34) {                       // top & bottom rows
        tile[tid] = 0.f;
        tile[33 * TS + tid] = 0.f;
    } else if (tid < 66) {                // left & right cols, rows 1..32
        int r = tid - 33;
        tile[r * TS] = 0.f;
        tile[r * TS + 33] = 0.f;
    }
    const float4 v = reinterpret_cast<const float4*>(xp)[tid];
    const int r = tid >> 3, c4 = tid & 7;
    float* d = &tile[(r + 1) * TS + c4 * 4 + 1];
    d[0] = v.x; d[1] = v.y; d[2] = v.z; d[3] = v.w;
}

// ---------------------------------------------------------------------------
// K1: depthwise 3x3 conv + bias, per-channel sum/sumsq (BN1 stats).
// One block per (n, c) plane. Block 0 also zeros the BN2 accumulators.
// ---------------------------------------------------------------------------
__global__ void __launch_bounds__(256) k_conv_stats(
    const float* __restrict__ x, const float* __restrict__ cw,
    const float* __restrict__ cb)
{
    const int n = blockIdx.x >> 8;
    const int c = blockIdx.x & (CC - 1);
    const float* xp = x + (size_t)(n * CC + c) * HW;

    if (blockIdx.x == 0) {  // zero BN2 stats for this launch (K1 never touches them)
        g_sum2[threadIdx.x] = 0.0; g_sumsq2[threadIdx.x] = 0.0;
    }

    __shared__ float tile[34 * TS];
    load_plane(xp, tile);

    float wgt[9];
    #pragma unroll
    for (int i = 0; i < 9; i++) wgt[i] = __ldg(&cw[c * 9 + i]);
    const float bias = __ldg(&cb[c]);
    __syncthreads();

    float s = 0.f, ss = 0.f;
    #pragma unroll
    for (int k = 0; k < 4; k++) {
        const int p = threadIdx.x + k * 256;
        const int r = p >> 5, q = p & 31;
        const float* t0 = &tile[r * TS + q];
        float acc = bias
            + wgt[0] * t0[0]      + wgt[1] * t0[1]      + wgt[2] * t0[2]
            + wgt[3] * t0[TS]     + wgt[4] * t0[TS+1]   + wgt[5] * t0[TS+2]
            + wgt[6] * t0[2*TS]   + wgt[7] * t0[2*TS+1] + wgt[8] * t0[2*TS+2];
        s += acc; ss += acc * acc;
    }
    block_reduce2(s, ss);
    if (threadIdx.x == 0) {
        atomicAdd(&g_sum1[c], (double)s);
        atomicAdd(&g_sumsq1[c], (double)ss);
    }
}

// ---------------------------------------------------------------------------
// K3: recompute conv for all 4 timesteps, apply BN1 (folded), run LIF,
// pack spikes as bits (staged in smem, coalesced store), accumulate BN2 stats.
// One block per (b, c).
// ---------------------------------------------------------------------------
__global__ void __launch_bounds__(256) k_lif(
    const float* __restrict__ x, const float* __restrict__ cw,
    const float* __restrict__ cb, const float* __restrict__ g1,
    const float* __restrict__ b1)
{
    const int b = blockIdx.x >> 8;
    const int c = blockIdx.x & (CC - 1);

    __shared__ float tile[TT][34 * TS];
    __shared__ unsigned s_spk[TT][32];
    __shared__ float s_scale1, s_shift1;

    #pragma unroll
    for (int t = 0; t < TT; t++)
        load_plane(x + (size_t)((t * BB + b) * CC + c) * HW, tile[t]);

    float wgt[9];
    #pragma unroll
    for (int i = 0; i < 9; i++) wgt[i] = __ldg(&cw[c * 9 + i]);

    if (threadIdx.x == 0) {
        double m   = g_sum1[c] * (1.0 / NSTAT);
        double var = g_sumsq1[c] * (1.0 / NSTAT) - m * m;
        float  sc  = __ldg(&g1[c]) * (float)rsqrt(var + EPSV);
        s_scale1 = sc;
        s_shift1 = __ldg(&b1[c]) + (__ldg(&cb[c]) - (float)m) * sc;
    }
    __syncthreads();
    const float scale1 = s_scale1, shift1 = s_shift1;

    const int warp = threadIdx.x >> 5;
    const int lane = threadIdx.x & 31;

    float s2 = 0.f, ss2 = 0.f;
    #pragma unroll
    for (int k = 0; k < 4; k++) {
        const int r = warp * 4 + k;   // output row
        const int q = lane;           // output col
        float v = 0.f;                // membrane potential
        #pragma unroll
        for (int t = 0; t < TT; t++) {
            const float* t0 = &tile[t][r * TS + q];
            float conv =
                  wgt[0] * t0[0]      + wgt[1] * t0[1]      + wgt[2] * t0[2]
                + wgt[3] * t0[TS]     + wgt[4] * t0[TS+1]   + wgt[5] * t0[TS+2]
                + wgt[6] * t0[2*TS]   + wgt[7] * t0[2*TS+1] + wgt[8] * t0[2*TS+2];
            float y = conv * scale1 + shift1;
            float h = 0.5f * (v + y);            // v + (y - v)/tau, tau = 2
            bool  fire = (h >= 1.0f);
            v = fire ? 0.f : h;                  // hard reset
            float z = (fire ? 1.f : 0.f) + t0[TS + 1];  // spike + x (center)
            s2 += z; ss2 += z * z;
            unsigned m = __ballot_sync(0xffffffffu, fire);
            if (lane == 0) s_spk[t][r] = m;
        }
    }
    block_reduce2(s2, ss2);
    __syncthreads();  // s_spk complete (block_reduce2 already synced once; be safe)
    if (threadIdx.x < TT * 32) {
        const int t = threadIdx.x >> 5, r = threadIdx.x & 31;
        g_spk[((size_t)(t * BB + b) * CC + c) * 32 + r] = s_spk[t][r];
    }
    if (threadIdx.x == 0) {
        atomicAdd(&g_sum2[c], (double)s2);
        atomicAdd(&g_sumsq2[c], (double)ss2);
    }
}

// ---------------------------------------------------------------------------
// K4: out = BN2(spike + x). One block = one (n,c) plane (1024 elems),
// so BN2 params are computed once per block. Block 0 zeros BN1 stats
// for the next launch (K4 never touches them).
// ---------------------------------------------------------------------------
__global__ void __launch_bounds__(256) k_bn2(
    const float* __restrict__ x, const float* __restrict__ g2,
    const float* __restrict__ b2, float* __restrict__ out)
{
    __shared__ float s_scale, s_shift;
    const int c = blockIdx.x & (CC - 1);

    if (threadIdx.x == 0) {
        double m   = g_sum2[c] * (1.0 / NSTAT);
        double var = g_sumsq2[c] * (1.0 / NSTAT) - m * m;
        float  sc  = __ldg(&g2[c]) * (float)rsqrt(var + EPSV);
        s_scale = sc;
        s_shift = __ldg(&b2[c]) - (float)m * sc;
    }
    if (blockIdx.x == 0) {  // reset BN1 stats for next launch
        g_sum1[threadIdx.x] = 0.0; g_sumsq1[threadIdx.x] = 0.0;
    }
    __syncthreads();
    const float scale2 = s_scale, shift2 = s_shift;

    const unsigned i4 = blockIdx.x * 256u + threadIdx.x;  // float4 index
    const unsigned e  = i4 * 4u;                          // element index

    const float4 xv = reinterpret_cast<const float4*>(x)[i4];
    const unsigned wbits = g_spk[e >> 5];
    const int l = e & 31;

    float4 o;
    o.x = (xv.x + (float)((wbits >> (l + 0)) & 1u)) * scale2 + shift2;
    o.y = (xv.y + (float)((wbits >> (l + 1)) & 1u)) * scale2 + shift2;
    o.z = (xv.z + (float)((wbits >> (l + 2)) & 1u)) * scale2 + shift2;
    o.w = (xv.w + (float)((wbits >> (l + 3)) & 1u)) * scale2 + shift2;
    reinterpret_cast<float4*>(out)[i4] = o;
}

// ---------------------------------------------------------------------------
// Launch: 3 kernels, stream-ordered (kernel boundaries = global-stat barriers).
// Stat accumulators are double, zero at module load; each launch leaves
// g_sum1/g_sumsq1 zeroed (end of K4) and zeros g_sum2/g_sumsq2 in K1.
// ---------------------------------------------------------------------------
extern "C" void kernel_launch(void* const* d_in, const int* in_sizes, int n_in,
                              void* d_out, int out_size) {
    const float* x  = (const float*)d_in[0];
    const float* cw = (const float*)d_in[1];
    const float* cb = (const float*)d_in[2];
    const float* g1 = (const float*)d_in[3];
    const float* b1 = (const float*)d_in[4];
    const float* g2 = (const float*)d_in[5];
    const float* b2 = (const float*)d_in[6];
    float* out = (float*)d_out;

    k_conv_stats<<<TB * CC, 256>>>(x, cw, cb);           // 32768 blocks
    k_lif<<<BB * CC, 256>>>(x, cw, cb, g1, b1);          // 8192 blocks
    k_bn2<<<TB * CC, 256>>>(x, g2, b2, out);             // 32768 blocks
}

// round 3
// speedup vs baseline: 2.0898x; 1.2676x over previous
#include <cuda_runtime.h>

// Problem constants (fixed shapes from reference setup_inputs)
#define TT 4
#define BB 32
#define CC 256
#define HW 1024               // 32*32 plane
#define TB 128                // TT*BB
#define NSTAT 131072.0        // TB*HW
#define EPSV 1e-5
#define TSTRIDE (BB*CC*HW)    // element stride between timesteps = 8388608

// Per-channel stat accumulators (double) + packed spike bits (4 MB)
__device__ double g_sum1[CC], g_sumsq1[CC], g_sum2[CC], g_sumsq2[CC];
__device__ unsigned g_spk[(TT * BB * CC * HW) / 32];

// ---------------------------------------------------------------------------
// K1: depthwise 3x3 conv + bias, per-channel sum/sumsq (BN1 stats).
// One WARP per (n,c) plane. Register-only conv: lane = column, iterate rows,
// horizontal neighbors via shuffle, vertical via rolling accumulators.
// ---------------------------------------------------------------------------
__global__ void __launch_bounds__(256) k_conv_stats(
    const float* __restrict__ x, const float* __restrict__ cw,
    const float* __restrict__ cb)
{
    const int warp = threadIdx.x >> 5, lane = threadIdx.x & 31;
    const int plane = blockIdx.x * 8 + warp;   // 0..32767 = n*CC + c
    const int c = plane & (CC - 1);
    const float* xp = x + (size_t)plane * HW;

    if (blockIdx.x == 0) {  // zero BN2 stats for this launch (K1 never reads them)
        g_sum2[threadIdx.x] = 0.0; g_sumsq2[threadIdx.x] = 0.0;
    }

    float w[9];
    #pragma unroll
    for (int i = 0; i < 9; i++) w[i] = __ldg(&cw[c * 9 + i]);
    const float bias = __ldg(&cb[c]);

    float acc0 = 0.f, acc1 = 0.f, s = 0.f, ss = 0.f;
    #pragma unroll 8
    for (int r = 0; r < 32; r++) {
        float v = __ldg(xp + r * 32 + lane);
        float hl = __shfl_up_sync(0xffffffffu, v, 1);   if (lane == 0)  hl = 0.f;
        float hr = __shfl_down_sync(0xffffffffu, v, 1); if (lane == 31) hr = 0.f;
        float a = w[0]*hl + w[1]*v + w[2]*hr;   // top contribution (to out r+1)
        float m = w[3]*hl + w[4]*v + w[5]*hr;   // mid (to out r)
        float d = w[6]*hl + w[7]*v + w[8]*hr;   // bottom (to out r-1)
        if (r) {                                 // out row r-1 complete
            float y = acc0 + d + bias;
            s += y; ss = fmaf(y, y, ss);
        }
        acc0 = acc1 + m;
        acc1 = a;
    }
    {   // out row 31 complete (bottom halo = 0)
        float y = acc0 + bias;
        s += y; ss = fmaf(y, y, ss);
    }
    #pragma unroll
    for (int o = 16; o > 0; o >>= 1) {
        s  += __shfl_xor_sync(0xffffffffu, s, o);
        ss += __shfl_xor_sync(0xffffffffu, ss, o);
    }
    if (lane == 0) {
        atomicAdd(&g_sum1[c], (double)s);
        atomicAdd(&g_sumsq1[c], (double)ss);
    }
}

// ---------------------------------------------------------------------------
// K3: register conv for all 4 timesteps, BN1 folded, LIF fully in registers
// (membrane never leaves the lane), spikes packed via ballot, staged in smem,
// written coalesced. BN2 stats accumulated. One WARP per (b,c) plane.
// ---------------------------------------------------------------------------
__global__ void __launch_bounds__(256) k_lif(
    const float* __restrict__ x, const float* __restrict__ cw,
    const float* __restrict__ cb, const float* __restrict__ g1,
    const float* __restrict__ b1)
{
    __shared__ __align__(16) unsigned sp[8][TT][32];
    const int warp = threadIdx.x >> 5, lane = threadIdx.x & 31;
    const int plane = blockIdx.x * 8 + warp;   // 0..8191 = b*CC + c
    const int c = plane & (CC - 1);
    const float* xp = x + (size_t)plane * HW;  // x[(t*BB+b)*CC+c] = t*TSTRIDE + plane

    float w[9];
    #pragma unroll
    for (int i = 0; i < 9; i++) w[i] = __ldg(&cw[c * 9 + i]);

    // BN1 params (broadcast loads; every lane computes the same thing)
    const double mu  = g_sum1[c] * (1.0 / NSTAT);
    const double var = g_sumsq1[c] * (1.0 / NSTAT) - mu * mu;
    const float scale1 = __ldg(&g1[c]) * (float)rsqrt(var + EPSV);
    const float shift1 = __ldg(&b1[c]) + (__ldg(&cb[c]) - (float)mu) * scale1;

    float acc0[TT], acc1[TT], xc[TT];
    #pragma unroll
    for (int t = 0; t < TT; t++) { acc0[t] = 0.f; acc1[t] = 0.f; xc[t] = 0.f; }
    float s2 = 0.f, ss2 = 0.f;

    #pragma unroll 2
    for (int r = 0; r < 32; r++) {
        float yrow[TT], vcur[TT];
        #pragma unroll
        for (int t = 0; t < TT; t++) {
            float v = __ldg(xp + (size_t)t * TSTRIDE + r * 32 + lane);
            float hl = __shfl_up_sync(0xffffffffu, v, 1);   if (lane == 0)  hl = 0.f;
            float hr = __shfl_down_sync(0xffffffffu, v, 1); if (lane == 31) hr = 0.f;
            float a = w[0]*hl + w[1]*v + w[2]*hr;
            float m = w[3]*hl + w[4]*v + w[5]*hr;
            float d = w[6]*hl + w[7]*v + w[8]*hr;
            yrow[t] = acc0[t] + d;       // out row r-1 conv (valid when r>=1)
            acc0[t] = acc1[t] + m;
            acc1[t] = a;
            vcur[t] = v;
        }
        if (r) {                          // LIF at output row r-1
            float vm = 0.f;
            #pragma unroll
            for (int t = 0; t < TT; t++) {
                float y = fmaf(yrow[t], scale1, shift1);
                float h = fmaf(y - vm, 0.5f, vm);          // v + (y-v)/tau
                bool fire = (h >= 1.0f);
                vm = fire ? 0.f : h;                        // hard reset
                unsigned mb = __ballot_sync(0xffffffffu, fire);
                if (lane == 0) sp[warp][t][r - 1] = mb;
                float z = (fire ? 1.f : 0.f) + xc[t];       // spike + x(center)
                s2 += z; ss2 = fmaf(z, z, ss2);
            }
        }
        #pragma unroll
        for (int t = 0; t < TT; t++) xc[t] = vcur[t];
    }
    {   // output row 31 (bottom halo = 0): conv = acc0
        float vm = 0.f;
        #pragma unroll
        for (int t = 0; t < TT; t++) {
            float y = fmaf(acc0[t], scale1, shift1);
            float h = fmaf(y - vm, 0.5f, vm);
            bool fire = (h >= 1.0f);
            vm = fire ? 0.f : h;
            unsigned mb = __ballot_sync(0xffffffffu, fire);
            if (lane == 0) sp[warp][t][31] = mb;
            float z = (fire ? 1.f : 0.f) + xc[t];
            s2 += z; ss2 = fmaf(z, z, ss2);
        }
    }
    #pragma unroll
    for (int o = 16; o > 0; o >>= 1) {
        s2  += __shfl_xor_sync(0xffffffffu, s2, o);
        ss2 += __shfl_xor_sync(0xffffffffu, ss2, o);
    }
    if (lane == 0) {
        atomicAdd(&g_sum2[c], (double)s2);
        atomicAdd(&g_sumsq2[c], (double)ss2);
    }
    __syncthreads();
    // Coalesced spike write: block covers 8 consecutive c for one b and all t.
    // word(t,b,c,row) = t*262144 + b*8192 + c*32 + row; our 8 c's are contiguous,
    // so per t the block owns 256 consecutive words -> uint4 per thread.
    {
        const int t = threadIdx.x >> 6;          // 0..3
        const int j = threadIdx.x & 63;          // 0..63
        const int widx = j * 4;                  // 0..252, word within 256-group
        const int wsrc = widx >> 5;              // source warp slot 0..7
        const int rsrc = widx & 31;              // source row (multiple of 4)
        uint4 val = *reinterpret_cast<const uint4*>(&sp[wsrc][t][rsrc]);
        const int b0 = (blockIdx.x * 8) >> 8;
        const int c0 = (blockIdx.x * 8) & (CC - 1);
        size_t gw = (size_t)t * (BB * CC * 32) + (size_t)b0 * (CC * 32)
                  + (size_t)c0 * 32 + widx;
        *reinterpret_cast<uint4*>(g_spk + gw) = val;
    }
}

// ---------------------------------------------------------------------------
// K4: out = BN2(spike + x). One block = one (n,c) plane; params computed once.
// Block 0 zeros BN1 stats for the next launch (K4 never touches them).
// ---------------------------------------------------------------------------
__global__ void __launch_bounds__(256) k_bn2(
    const float* __restrict__ x, const float* __restrict__ g2,
    const float* __restrict__ b2, float* __restrict__ out)
{
    __shared__ float s_scale, s_shift;
    const int c = blockIdx.x & (CC - 1);

    if (threadIdx.x == 0) {
        double m   = g_sum2[c] * (1.0 / NSTAT);
        double var = g_sumsq2[c] * (1.0 / NSTAT) - m * m;
        float  sc  = __ldg(&g2[c]) * (float)rsqrt(var + EPSV);
        s_scale = sc;
        s_shift = __ldg(&b2[c]) - (float)m * sc;
    }
    if (blockIdx.x == 0) {  // reset BN1 stats for next launch
        g_sum1[threadIdx.x] = 0.0; g_sumsq1[threadIdx.x] = 0.0;
    }
    __syncthreads();
    const float scale2 = s_scale, shift2 = s_shift;

    const unsigned i4 = blockIdx.x * 256u + threadIdx.x;  // float4 index
    const unsigned e  = i4 * 4u;                          // element index

    const float4 xv = reinterpret_cast<const float4*>(x)[i4];
    const unsigned wbits = g_spk[e >> 5];
    const int l = e & 31;

    float4 o;
    o.x = (xv.x + (float)((wbits >> (l + 0)) & 1u)) * scale2 + shift2;
    o.y = (xv.y + (float)((wbits >> (l + 1)) & 1u)) * scale2 + shift2;
    o.z = (xv.z + (float)((wbits >> (l + 2)) & 1u)) * scale2 + shift2;
    o.w = (xv.w + (float)((wbits >> (l + 3)) & 1u)) * scale2 + shift2;
    reinterpret_cast<float4*>(out)[i4] = o;
}

// ---------------------------------------------------------------------------
// Launch: 3 kernels, stream-ordered (kernel boundaries = global-stat barriers).
// ---------------------------------------------------------------------------
extern "C" void kernel_launch(void* const* d_in, const int* in_sizes, int n_in,
                              void* d_out, int out_size) {
    const float* x  = (const float*)d_in[0];
    const float* cw = (const float*)d_in[1];
    const float* cb = (const float*)d_in[2];
    const float* g1 = (const float*)d_in[3];
    const float* b1 = (const float*)d_in[4];
    const float* g2 = (const float*)d_in[5];
    const float* b2 = (const float*)d_in[6];
    float* out = (float*)d_out;

    k_conv_stats<<<(TB * CC) / 8, 256>>>(x, cw, cb);   // 4096 blocks, warp/plane
    k_lif<<<(BB * CC) / 8, 256>>>(x, cw, cb, g1, b1);  // 1024 blocks, warp/plane
    k_bn2<<<TB * CC, 256>>>(x, g2, b2, out);           // 32768 blocks
}

// round 4
// speedup vs baseline: 2.1651x; 1.0360x over previous
#include <cuda_runtime.h>

// Fixed shapes from reference setup_inputs
#define TT 4
#define BB 32
#define CC 256
#define HW 1024               // 32x32 plane
#define TB 128                // TT*BB
#define NSTAT 131072.0        // TB*HW
#define EPSV 1e-5
#define TSTRIDE (BB*CC*HW)    // element stride between timesteps

// Per-channel stat accumulators (double) + packed spike bits (4 MB).
// g_spk layout (matched between K3 producer and K4 consumer):
//   word = plane*32 + cg*4 + k   (plane=(t*BB+b)*CC+c, cg=col>>2, k=row>>3)
//   bit  = (row&7)*4 + j         (j = col&3)
__device__ double g_sum1[CC], g_sumsq1[CC], g_sum2[CC], g_sumsq2[CC];
__device__ unsigned g_spk[(TT * BB * CC * HW) / 32];

// Horizontal 3-tap conv on a float4 strip with scalar edge neighbors.
__device__ __forceinline__ float4 hconv(float w0, float w1, float w2,
                                        float l, float4 v, float r) {
    float4 o;
    o.x = fmaf(w0, l,   fmaf(w1, v.x, w2 * v.y));
    o.y = fmaf(w0, v.x, fmaf(w1, v.y, w2 * v.z));
    o.z = fmaf(w0, v.y, fmaf(w1, v.z, w2 * v.w));
    o.w = fmaf(w0, v.z, fmaf(w1, v.w, w2 * r));
    return o;
}

// ---------------------------------------------------------------------------
// K1: depthwise 3x3 conv + bias, per-channel sum/sumsq (BN1 stats).
// Warp = 4 planes; lane>>3 = plane subgroup, lane&7 = column group (float4).
// Rolling vertical accumulators; zero LDS/STS.
// ---------------------------------------------------------------------------
__global__ void __launch_bounds__(256) k_conv_stats(
    const float* __restrict__ x, const float* __restrict__ cw,
    const float* __restrict__ cb)
{
    const int lane = threadIdx.x & 31, warp = threadIdx.x >> 5;
    const int cg = lane & 7;                        // column group
    const int plane = blockIdx.x * 32 + warp * 4 + (lane >> 3);
    const int c = plane & (CC - 1);
    const float* xp = x + (size_t)plane * HW + cg * 4;

    if (blockIdx.x == 0) {  // zero BN2 stats (K1 never reads them)
        g_sum2[threadIdx.x] = 0.0; g_sumsq2[threadIdx.x] = 0.0;
    }

    float w[9];
    #pragma unroll
    for (int i = 0; i < 9; i++) w[i] = __ldg(&cw[c * 9 + i]);
    const float bias = __ldg(&cb[c]);

    float4 acc0 = {0,0,0,0}, acc1 = {0,0,0,0};
    float s = 0.f, ss = 0.f;

    #pragma unroll 8
    for (int r = 0; r < 32; r++) {
        const float4 v = __ldg(reinterpret_cast<const float4*>(xp + r * 32));
        float hl = __shfl_up_sync(0xffffffffu, v.w, 1);   if (cg == 0) hl = 0.f;
        float hr = __shfl_down_sync(0xffffffffu, v.x, 1); if (cg == 7) hr = 0.f;
        float4 a = hconv(w[0], w[1], w[2], hl, v, hr);
        float4 m = hconv(w[3], w[4], w[5], hl, v, hr);
        float4 d = hconv(w[6], w[7], w[8], hl, v, hr);
        if (r) {  // output row r-1 complete
            float yx = acc0.x + d.x + bias, yy = acc0.y + d.y + bias;
            float yz = acc0.z + d.z + bias, yw = acc0.w + d.w + bias;
            s += (yx + yy) + (yz + yw);
            ss = fmaf(yx, yx, fmaf(yy, yy, fmaf(yz, yz, fmaf(yw, yw, ss))));
        }
        acc0.x = acc1.x + m.x; acc0.y = acc1.y + m.y;
        acc0.z = acc1.z + m.z; acc0.w = acc1.w + m.w;
        acc1 = a;
    }
    {   // output row 31 (bottom halo = 0)
        float yx = acc0.x + bias, yy = acc0.y + bias;
        float yz = acc0.z + bias, yw = acc0.w + bias;
        s += (yx + yy) + (yz + yw);
        ss = fmaf(yx, yx, fmaf(yy, yy, fmaf(yz, yz, fmaf(yw, yw, ss))));
    }
    #pragma unroll
    for (int o = 4; o > 0; o >>= 1) {  // reduce within 8-lane plane group
        s  += __shfl_xor_sync(0xffffffffu, s, o);
        ss += __shfl_xor_sync(0xffffffffu, ss, o);
    }
    if (cg == 0) {
        atomicAdd(&g_sum1[c], (double)s);
        atomicAdd(&g_sumsq1[c], (double)ss);
    }
}

// ---------------------------------------------------------------------------
// K3: float4-strip conv for all 4 timesteps, BN1 folded, LIF in registers,
// spike nibbles packed per-thread, BN2 stats. Warp = 4 (b,c) planes.
// ---------------------------------------------------------------------------
__global__ void __launch_bounds__(128) k_lif(
    const float* __restrict__ x, const float* __restrict__ cw,
    const float* __restrict__ cb, const float* __restrict__ g1,
    const float* __restrict__ b1)
{
    const int lane = threadIdx.x & 31, warp = threadIdx.x >> 5;
    const int cg = lane & 7;
    const int plane = blockIdx.x * 16 + warp * 4 + (lane >> 3); // b*CC + c
    const int c = plane & (CC - 1);
    const float* xp = x + (size_t)plane * HW + cg * 4;

    float w[9];
    #pragma unroll
    for (int i = 0; i < 9; i++) w[i] = __ldg(&cw[c * 9 + i]);

    const double mu  = g_sum1[c] * (1.0 / NSTAT);
    const double var = g_sumsq1[c] * (1.0 / NSTAT) - mu * mu;
    const float scale1 = __ldg(&g1[c]) * (float)rsqrt(var + EPSV);
    const float shift1 = __ldg(&b1[c]) + (__ldg(&cb[c]) - (float)mu) * scale1;

    float4 acc0[TT], acc1[TT], vprev[TT];
    unsigned spw[TT];
    #pragma unroll
    for (int t = 0; t < TT; t++) {
        acc0[t] = make_float4(0,0,0,0); acc1[t] = make_float4(0,0,0,0);
        vprev[t] = make_float4(0,0,0,0); spw[t] = 0u;
    }
    float s2 = 0.f, ss2 = 0.f;

    #pragma unroll 2
    for (int r = 0; r < 32; r++) {
        float4 yrow[TT];
        float4 vcur[TT];
        #pragma unroll
        for (int t = 0; t < TT; t++) {
            const float4 v = __ldg(reinterpret_cast<const float4*>(
                                   xp + (size_t)t * TSTRIDE + r * 32));
            float hl = __shfl_up_sync(0xffffffffu, v.w, 1);   if (cg == 0) hl = 0.f;
            float hr = __shfl_down_sync(0xffffffffu, v.x, 1); if (cg == 7) hr = 0.f;
            float4 a = hconv(w[0], w[1], w[2], hl, v, hr);
            float4 m = hconv(w[3], w[4], w[5], hl, v, hr);
            float4 d = hconv(w[6], w[7], w[8], hl, v, hr);
            yrow[t].x = acc0[t].x + d.x; yrow[t].y = acc0[t].y + d.y;
            yrow[t].z = acc0[t].z + d.z; yrow[t].w = acc0[t].w + d.w;
            acc0[t].x = acc1[t].x + m.x; acc0[t].y = acc1[t].y + m.y;
            acc0[t].z = acc1[t].z + m.z; acc0[t].w = acc1[t].w + m.w;
            acc1[t] = a;
            vcur[t] = v;
        }
        if (r) {
            const int ro = r - 1;
            float4 vm = make_float4(0,0,0,0);
            #pragma unroll
            for (int t = 0; t < TT; t++) {
                float yx = fmaf(yrow[t].x, scale1, shift1);
                float yy = fmaf(yrow[t].y, scale1, shift1);
                float yz = fmaf(yrow[t].z, scale1, shift1);
                float yw = fmaf(yrow[t].w, scale1, shift1);
                float hx = fmaf(yx - vm.x, 0.5f, vm.x);
                float hy = fmaf(yy - vm.y, 0.5f, vm.y);
                float hz = fmaf(yz - vm.z, 0.5f, vm.z);
                float hw = fmaf(yw - vm.w, 0.5f, vm.w);
                bool f0 = hx >= 1.f, f1 = hy >= 1.f, f2 = hz >= 1.f, f3 = hw >= 1.f;
                vm.x = f0 ? 0.f : hx; vm.y = f1 ? 0.f : hy;
                vm.z = f2 ? 0.f : hz; vm.w = f3 ? 0.f : hw;
                unsigned nib = (f0 ? 1u : 0u) | (f1 ? 2u : 0u)
                             | (f2 ? 4u : 0u) | (f3 ? 8u : 0u);
                spw[t] |= nib << ((ro & 7) * 4);
                float zx = (f0 ? 1.f : 0.f) + vprev[t].x;
                float zy = (f1 ? 1.f : 0.f) + vprev[t].y;
                float zz = (f2 ? 1.f : 0.f) + vprev[t].z;
                float zw = (f3 ? 1.f : 0.f) + vprev[t].w;
                s2 += (zx + zy) + (zz + zw);
                ss2 = fmaf(zx, zx, fmaf(zy, zy, fmaf(zz, zz, fmaf(zw, zw, ss2))));
            }
            if ((ro & 7) == 7) {  // flush rows ro-7..ro (ro = 7,15,23)
                const int k = ro >> 3;
                #pragma unroll
                for (int t = 0; t < TT; t++) {
                    g_spk[((size_t)(t * BB * CC) + plane) * 32 + cg * 4 + k] = spw[t];
                    spw[t] = 0u;
                }
            }
        }
        #pragma unroll
        for (int t = 0; t < TT; t++) vprev[t] = vcur[t];
    }
    {   // output row 31 (conv = acc0; bottom halo = 0)
        float4 vm = make_float4(0,0,0,0);
        #pragma unroll
        for (int t = 0; t < TT; t++) {
            float yx = fmaf(acc0[t].x, scale1, shift1);
            float yy = fmaf(acc0[t].y, scale1, shift1);
            float yz = fmaf(acc0[t].z, scale1, shift1);
            float yw = fmaf(acc0[t].w, scale1, shift1);
            float hx = fmaf(yx - vm.x, 0.5f, vm.x);
            float hy = fmaf(yy - vm.y, 0.5f, vm.y);
            float hz = fmaf(yz - vm.z, 0.5f, vm.z);
            float hw = fmaf(yw - vm.w, 0.5f, vm.w);
            bool f0 = hx >= 1.f, f1 = hy >= 1.f, f2 = hz >= 1.f, f3 = hw >= 1.f;
            vm.x = f0 ? 0.f : hx; vm.y = f1 ? 0.f : hy;
            vm.z = f2 ? 0.f : hz; vm.w = f3 ? 0.f : hw;
            unsigned nib = (f0 ? 1u : 0u) | (f1 ? 2u : 0u)
                         | (f2 ? 4u : 0u) | (f3 ? 8u : 0u);
            spw[t] |= nib << 28;  // (31&7)*4
            float zx = (f0 ? 1.f : 0.f) + vprev[t].x;
            float zy = (f1 ? 1.f : 0.f) + vprev[t].y;
            float zz = (f2 ? 1.f : 0.f) + vprev[t].z;
            float zw = (f3 ? 1.f : 0.f) + vprev[t].w;
            s2 += (zx + zy) + (zz + zw);
            ss2 = fmaf(zx, zx, fmaf(zy, zy, fmaf(zz, zz, fmaf(zw, zw, ss2))));
            g_spk[((size_t)(t * BB * CC) + plane) * 32 + cg * 4 + 3] = spw[t];
        }
    }
    #pragma unroll
    for (int o = 4; o > 0; o >>= 1) {  // reduce within 8-lane plane group
        s2  += __shfl_xor_sync(0xffffffffu, s2, o);
        ss2 += __shfl_xor_sync(0xffffffffu, ss2, o);
    }
    if (cg == 0) {
        atomicAdd(&g_sum2[c], (double)s2);
        atomicAdd(&g_sumsq2[c], (double)ss2);
    }
}

// ---------------------------------------------------------------------------
// K4: out = BN2(spike + x). One block = one (t,b,c) plane; params once/block.
// Block 0 zeros BN1 stats for the next launch.
// ---------------------------------------------------------------------------
__global__ void __launch_bounds__(256) k_bn2(
    const float* __restrict__ x, const float* __restrict__ g2,
    const float* __restrict__ b2, float* __restrict__ out)
{
    __shared__ float s_scale, s_shift;
    const int c = blockIdx.x & (CC - 1);

    if (threadIdx.x == 0) {
        double m   = g_sum2[c] * (1.0 / NSTAT);
        double var = g_sumsq2[c] * (1.0 / NSTAT) - m * m;
        float  sc  = __ldg(&g2[c]) * (float)rsqrt(var + EPSV);
        s_scale = sc;
        s_shift = __ldg(&b2[c]) - (float)m * sc;
    }
    if (blockIdx.x == 0) {  // reset BN1 stats for next launch
        g_sum1[threadIdx.x] = 0.0; g_sumsq1[threadIdx.x] = 0.0;
    }
    __syncthreads();
    const float scale2 = s_scale, shift2 = s_shift;

    const unsigned i4 = blockIdx.x * 256u + threadIdx.x;  // float4 index
    const float4 xv = reinterpret_cast<const float4*>(x)[i4];

    // word = plane*32 + cg*4 + k ; plane=i4>>8, cg=i4&7, k=(i4>>6)&3
    const unsigned widx = (i4 >> 8) * 32u + (i4 & 7u) * 4u + ((i4 >> 6) & 3u);
    const unsigned wbits = g_spk[widx];
    const int sh = (int)((i4 >> 1) & 0x1Cu);  // ((row&7)*4)

    float4 o;
    o.x = (xv.x + (float)((wbits >> (sh + 0)) & 1u)) * scale2 + shift2;
    o.y = (xv.y + (float)((wbits >> (sh + 1)) & 1u)) * scale2 + shift2;
    o.z = (xv.z + (float)((wbits >> (sh + 2)) & 1u)) * scale2 + shift2;
    o.w = (xv.w + (float)((wbits >> (sh + 3)) & 1u)) * scale2 + shift2;
    reinterpret_cast<float4*>(out)[i4] = o;
}

// ---------------------------------------------------------------------------
extern "C" void kernel_launch(void* const* d_in, const int* in_sizes, int n_in,
                              void* d_out, int out_size) {
    const float* x  = (const float*)d_in[0];
    const float* cw = (const float*)d_in[1];
    const float* cb = (const float*)d_in[2];
    const float* g1 = (const float*)d_in[3];
    const float* b1 = (const float*)d_in[4];
    const float* g2 = (const float*)d_in[5];
    const float* b2 = (const float*)d_in[6];
    float* out = (float*)d_out;

    k_conv_stats<<<(TB * CC) / 32, 256>>>(x, cw, cb);    // 1024 blocks
    k_lif<<<(BB * CC) / 16, 128>>>(x, cw, cb, g1, b1);   // 512 blocks
    k_bn2<<<TB * CC, 256>>>(x, g2, b2, out);             // 32768 blocks
}